// round 7
// baseline (speedup 1.0000x reference)
#include <cuda_runtime.h>
#include <cuda_bf16.h>

// ---------------------------------------------------------------------------
// DetectionLoss (YOLOv5-style), two kernels (R5 skeleton), no contended
// atomics. This round: __ldcs streaming loads on the strided obj sweep (test:
// suppress 128B L2 line promotion -> sector-granular DRAM traffic) + 2x grid
// (825 obj blocks, 2 loads/thread) to lift occupancy off the grid-size cap.
//   p3 [16,3,80,80,85] p4 [16,3,40,40,85] p5 [16,3,20,20,85]
// Output: scalar f32.
//
// BCE(x,t) = softplus(x) - x*t  =>
//   obj_l = ( sum_all softplus(x4) - sum_{unique pos cells} x4 ) / Ncells_l
// ---------------------------------------------------------------------------

#define B_    16
#define M_    64
#define A_    3
#define NC_   80
#define CH_   85
#define NBOX  (B_ * M_)               // 1024
#define CELLS0 (B_ * A_ * 80 * 80)    // 307200
#define CELLS1 (B_ * A_ * 40 * 40)    // 76800
#define CELLS2 (B_ * A_ * 20 * 20)    // 19200

#define TPB 256
#define POS_BLOCKS 12
#define OBJ_BLK0 (CELLS0 / (TPB * 2))   // 600  (512 cells, 2 loads/thread)
#define OBJ_BLK1 (CELLS1 / (TPB * 2))   // 150
#define OBJ_BLK2 (CELLS2 / TPB)         // 75   (256 cells, 1 load/thread)
#define OBJ_BLOCKS (OBJ_BLK0 + OBJ_BLK1 + OBJ_BLK2)   // 825
#define TOTAL_BLOCKS (POS_BLOCKS + OBJ_BLOCKS)        // 837
#define HASH_SZ 512

static __device__ float g_obj[OBJ_BLOCKS];
static __device__ float g_pcls[POS_BLOCKS];
static __device__ float g_pbox[POS_BLOCKS];
static __device__ float g_pngx[POS_BLOCKS];
static __device__ int   g_pnp [POS_BLOCKS];

__device__ __forceinline__ float softplusf(float x) {
    return fmaxf(x, 0.0f) + log1pf(expf(-fabsf(x)));
}

// ---------------------------------------------------------------------------
__global__ void __launch_bounds__(TPB)
dl_main_kernel(const float* __restrict__ p3,
               const float* __restrict__ p4,
               const float* __restrict__ p5,
               const float* __restrict__ boxes,
               const int*   __restrict__ labels,
               const unsigned char* __restrict__ valid,
               const float* __restrict__ anchors) {
    const int tid = threadIdx.x;

    if (blockIdx.x >= POS_BLOCKS) {
        // ======= obj softplus sweep: streaming loads, exact ranges ==========
        const int o = blockIdx.x - POS_BLOCKS;
        float acc;
        if (o < OBJ_BLK0) {
            const long c0 = (long)o * (TPB * 2) + tid;
            float v0 = __ldcs(&p3[(c0      ) * CH_ + 4]);
            float v1 = __ldcs(&p3[(c0 + TPB) * CH_ + 4]);
            acc = softplusf(v0) + softplusf(v1);
        } else if (o < OBJ_BLK0 + OBJ_BLK1) {
            const long c0 = (long)(o - OBJ_BLK0) * (TPB * 2) + tid;
            float v0 = __ldcs(&p4[(c0      ) * CH_ + 4]);
            float v1 = __ldcs(&p4[(c0 + TPB) * CH_ + 4]);
            acc = softplusf(v0) + softplusf(v1);
        } else {
            const long c0 = (long)(o - OBJ_BLK0 - OBJ_BLK1) * TPB + tid;
            acc = softplusf(__ldcs(&p5[c0 * CH_ + 4]));
        }

        __shared__ float s_w[TPB / 32];
#pragma unroll
        for (int s = 16; s > 0; s >>= 1)
            acc += __shfl_down_sync(0xFFFFFFFFu, acc, s);
        if ((tid & 31) == 0) s_w[tid >> 5] = acc;
        __syncthreads();
        if (tid < 32) {
            float r = (tid < TPB / 32) ? s_w[tid] : 0.0f;
#pragma unroll
            for (int s = 4; s > 0; s >>= 1)
                r += __shfl_down_sync(0xFFFFFFFFu, r, s);
            if (tid == 0) g_obj[o] = r;
        }
        return;
    }

    // ================= positives: 4 blocks per layer, 1 box/thread ==========
    __shared__ int   s_hash[HASH_SZ];
    __shared__ float s_rc[TPB / 32], s_rb[TPB / 32], s_rn[TPB / 32];
    __shared__ int   s_rp[TPB / 32];

#pragma unroll
    for (int k = 0; k < HASH_SZ / TPB; k++) s_hash[k * TPB + tid] = -1;
    __syncthreads();

    const int layer   = blockIdx.x >> 2;
    const int quarter = blockIdx.x & 3;
    const int i = quarter * TPB + tid;     // box index b*M + m
    const int b = i >> 6;
    const int g = 80 >> layer;
    const float gf = (float)g;
    const float* __restrict__ P = (layer == 0) ? p3 : (layer == 1) ? p4 : p5;
    const float aw0 = __ldg(&anchors[layer * 6 + 0]), ah0 = __ldg(&anchors[layer * 6 + 1]);
    const float aw1 = __ldg(&anchors[layer * 6 + 2]), ah1 = __ldg(&anchors[layer * 6 + 3]);
    const float aw2 = __ldg(&anchors[layer * 6 + 4]), ah2 = __ldg(&anchors[layer * 6 + 5]);

    const float x1 = boxes[i * 4 + 0];
    const float y1 = boxes[i * 4 + 1];
    const float x2 = boxes[i * 4 + 2];
    const float y2 = boxes[i * 4 + 3];
    const float cx = (x1 + x2) * 0.5f * gf;
    const float cy = (y1 + y2) * 0.5f * gf;
    const float w  = (x2 - x1) * gf;
    const float h  = (y2 - y1) * gf;

    const float wh = w * h;
    float best; int ba;
    {
        float in0 = fminf(w, aw0) * fminf(h, ah0);
        float i0  = in0 / (wh + aw0 * ah0 - in0 + 1e-6f);
        float in1 = fminf(w, aw1) * fminf(h, ah1);
        float i1  = in1 / (wh + aw1 * ah1 - in1 + 1e-6f);
        float in2 = fminf(w, aw2) * fminf(h, ah2);
        float i2  = in2 / (wh + aw2 * ah2 - in2 + 1e-6f);
        best = i0; ba = 0;
        if (i1 > best) { best = i1; ba = 1; }
        if (i2 > best) { best = i2; ba = 2; }
    }

    float cls_acc = 0.0f, box_acc = 0.0f, ngx_acc = 0.0f;
    int   np = 0;

    if (valid[i] && best > 0.5f) {
        int gx = (int)cx; gx = min(max(gx, 0), g - 1);
        int gy = (int)cy; gy = min(max(gy, 0), g - 1);
        const int  cell = ((b * A_ + ba) * g + gy) * g + gx;
        const long base = (long)cell * CH_;

        np = 1;

        const int lab = labels[i];
        float cl = 0.0f;
#pragma unroll 4
        for (int c = 0; c < NC_; c++)
            cl += softplusf(__ldg(&P[base + 5 + c]));
        cl -= __ldg(&P[base + 5 + lab]);
        cls_acc = cl;

        const float pcx0 = P[base + 0], pcy0 = P[base + 1];
        const float pw   = P[base + 2], ph   = P[base + 3];
        const float px1 = pcx0 - pw * 0.5f, py1 = pcy0 - ph * 0.5f;
        const float px2 = pcx0 + pw * 0.5f, py2 = pcy0 + ph * 0.5f;
        const float tx1 = cx - w * 0.5f, ty1 = cy - h * 0.5f;
        const float tx2 = cx + w * 0.5f, ty2 = cy + h * 0.5f;

        const float ix1 = fmaxf(px1, tx1), iy1 = fmaxf(py1, ty1);
        const float ix2 = fminf(px2, tx2), iy2 = fminf(py2, ty2);
        const float inter = fmaxf(ix2 - ix1, 0.0f) * fmaxf(iy2 - iy1, 0.0f);
        const float a1 = (px2 - px1) * (py2 - py1);
        const float a2 = (tx2 - tx1) * (ty2 - ty1);
        const float iou = inter / (a1 + a2 - inter + 1e-7f);

        const float pcx = (px1 + px2) * 0.5f, pcy = (py1 + py2) * 0.5f;
        const float tcx = (tx1 + tx2) * 0.5f, tcy = (ty1 + ty2) * 0.5f;
        const float cd  = (pcx - tcx) * (pcx - tcx) + (pcy - tcy) * (pcy - tcy);

        const float ex1 = fminf(px1, tx1), ey1 = fminf(py1, ty1);
        const float ex2 = fmaxf(px2, tx2), ey2 = fmaxf(py2, ty2);
        const float dd  = (ex2 - ex1) * (ex2 - ex1) + (ey2 - ey1) * (ey2 - ey1);

        box_acc = 1.0f - (iou - cd / (dd + 1e-7f));

        unsigned int hsh = (((unsigned int)cell * 2654435761u) >> 23) & (HASH_SZ - 1);
        bool owner = false;
        for (;;) {
            int old = atomicCAS(&s_hash[hsh], -1, cell);
            if (old == -1) { owner = true; break; }
            if (old == cell) break;
            hsh = (hsh + 1) & (HASH_SZ - 1);
        }
        if (owner) ngx_acc = -P[base + 4];
    }

#pragma unroll
    for (int s = 16; s > 0; s >>= 1) {
        cls_acc += __shfl_down_sync(0xFFFFFFFFu, cls_acc, s);
        box_acc += __shfl_down_sync(0xFFFFFFFFu, box_acc, s);
        ngx_acc += __shfl_down_sync(0xFFFFFFFFu, ngx_acc, s);
        np      += __shfl_down_sync(0xFFFFFFFFu, np, s);
    }
    if ((tid & 31) == 0) {
        s_rc[tid >> 5] = cls_acc;
        s_rb[tid >> 5] = box_acc;
        s_rn[tid >> 5] = ngx_acc;
        s_rp[tid >> 5] = np;
    }
    __syncthreads();
    if (tid < 32) {
        float rc = (tid < TPB / 32) ? s_rc[tid] : 0.0f;
        float rb = (tid < TPB / 32) ? s_rb[tid] : 0.0f;
        float rn = (tid < TPB / 32) ? s_rn[tid] : 0.0f;
        int   rp = (tid < TPB / 32) ? s_rp[tid] : 0;
#pragma unroll
        for (int s = 4; s > 0; s >>= 1) {
            rc += __shfl_down_sync(0xFFFFFFFFu, rc, s);
            rb += __shfl_down_sync(0xFFFFFFFFu, rb, s);
            rn += __shfl_down_sync(0xFFFFFFFFu, rn, s);
            rp += __shfl_down_sync(0xFFFFFFFFu, rp, s);
        }
        if (tid == 0) {
            g_pcls[blockIdx.x] = rc;
            g_pbox[blockIdx.x] = rb;
            g_pngx[blockIdx.x] = rn;
            g_pnp [blockIdx.x] = rp;
        }
    }
}

// ---------------------------------------------------------------------------
// One block, 1024 threads: one obj partial per thread (825 < 1024), segmented
// per-layer double accumulation, shuffle+smem tree reduce, fold pos partials.
__global__ void __launch_bounds__(1024)
dl_fin_kernel(float* __restrict__ out) {
    const int tid = threadIdx.x;

    double a0 = 0.0, a1 = 0.0, a2 = 0.0;
    if (tid < OBJ_BLOCKS) {
        const double v = (double)g_obj[tid];
        if (tid < OBJ_BLK0)                 a0 = v;
        else if (tid < OBJ_BLK0 + OBJ_BLK1) a1 = v;
        else                                a2 = v;
    }
#pragma unroll
    for (int s = 16; s > 0; s >>= 1) {
        a0 += __shfl_down_sync(0xFFFFFFFFu, a0, s);
        a1 += __shfl_down_sync(0xFFFFFFFFu, a1, s);
        a2 += __shfl_down_sync(0xFFFFFFFFu, a2, s);
    }
    __shared__ double s_f[3][32];
    if ((tid & 31) == 0) {
        s_f[0][tid >> 5] = a0;
        s_f[1][tid >> 5] = a1;
        s_f[2][tid >> 5] = a2;
    }
    __syncthreads();

    if (tid == 0) {
        double sp[3] = {0.0, 0.0, 0.0};
#pragma unroll
        for (int k = 0; k < 32; k++) {
            sp[0] += s_f[0][k];
            sp[1] += s_f[1][k];
            sp[2] += s_f[2][k];
        }
        const double ncell[3] = {(double)CELLS0, (double)CELLS1, (double)CELLS2};
        double cls = 0.0, obj = 0.0, box = 0.0;
#pragma unroll
        for (int l = 0; l < 3; l++) {
            double pc = 0.0, pb = 0.0, pn = 0.0;
            int np = 0;
#pragma unroll
            for (int q = 0; q < 4; q++) {
                pc += (double)g_pcls[l * 4 + q];
                pb += (double)g_pbox[l * 4 + q];
                pn += (double)g_pngx[l * 4 + q];
                np += g_pnp[l * 4 + q];
            }
            if (np > 0) {
                const double denom = (double)np;
                cls += pc / (denom * (double)NC_);
                obj += (sp[l] + pn) / ncell[l];
                box += pb / denom;
            }
        }
        out[0] = (float)(0.5 * cls + 1.0 * obj + 0.05 * box);
    }
}

// ---------------------------------------------------------------------------
extern "C" void kernel_launch(void* const* d_in, const int* in_sizes, int n_in,
                              void* d_out, int out_size) {
    const float*         p3      = (const float*)d_in[0];
    const float*         p4      = (const float*)d_in[1];
    const float*         p5      = (const float*)d_in[2];
    const float*         boxes   = (const float*)d_in[3];
    const int*           labels  = (const int*)d_in[4];
    const unsigned char* valid   = (const unsigned char*)d_in[5];
    const float*         anchors = (const float*)d_in[6];
    float*               out     = (float*)d_out;

    dl_main_kernel<<<TOTAL_BLOCKS, TPB>>>(p3, p4, p5, boxes, labels, valid,
                                          anchors);
    dl_fin_kernel<<<1, 1024>>>(out);
}

// round 8
// speedup vs baseline: 1.1936x; 1.1936x over previous
#include <cuda_runtime.h>
#include <cuda.h>
#include <cuda_bf16.h>

// ---------------------------------------------------------------------------
// DetectionLoss (YOLOv5-style), two kernels, no contended atomics.
// This round: obj sweep via TMA 2D boxes (32B per cell, L2_PROMOTION_NONE)
// instead of strided LDG (which measured 128B/cell of DRAM traffic).
//
// Layout trick: 4 cells = 1360B = 85*16B, so view pred as [N/4, 340 floats]
// (stride 1360B, 16B-multiple). Four boxes {8 floats x 256 rows} at x-offsets
// {0,84,168,256} cover ch4 of phases 0..3 at in-box positions {4,5,6,3}.
//
// BCE(x,t) = softplus(x) - x*t  =>
//   obj_l = ( sum_all softplus(x4) - sum_{unique pos cells} x4 ) / Ncells_l
//
// Grid (406 x 256): blocks 0..11 positives (R5 design), blocks 12..405 obj
// (1024 cells each; p5 last block partial). Fallback flag -> LDG path if the
// tensor-map encoder is unavailable. Fin kernel: 1 block x 512.
// ---------------------------------------------------------------------------

#define B_    16
#define M_    64
#define A_    3
#define NC_   80
#define CH_   85
#define NBOX  1024
#define CELLS0 307200
#define CELLS1 76800
#define CELLS2 19200

#define TPB 256
#define POS_BLOCKS 12
#define OBJ_BLK0 300                      // 1024 cells each (256 group-rows)
#define OBJ_BLK1 75
#define OBJ_BLK2 19                       // last block: 192 of 256 rows valid
#define OBJ_BLOCKS (OBJ_BLK0 + OBJ_BLK1 + OBJ_BLK2)   // 394
#define TOTAL_BLOCKS (POS_BLOCKS + OBJ_BLOCKS)        // 406
#define HASH_SZ 512

static __device__ float g_obj[OBJ_BLOCKS];
static __device__ float g_pcls[POS_BLOCKS];
static __device__ float g_pbox[POS_BLOCKS];
static __device__ float g_pngx[POS_BLOCKS];
static __device__ int   g_pnp [POS_BLOCKS];

__device__ __forceinline__ float softplusf(float x) {
    return fmaxf(x, 0.0f) + log1pf(expf(-fabsf(x)));
}

// ---------------------------------------------------------------------------
__global__ void __launch_bounds__(TPB)
dl_main_kernel(const __grid_constant__ CUtensorMap tm0,
               const __grid_constant__ CUtensorMap tm1,
               const __grid_constant__ CUtensorMap tm2,
               const int use_tma,
               const float* __restrict__ p3,
               const float* __restrict__ p4,
               const float* __restrict__ p5,
               const float* __restrict__ boxes,
               const int*   __restrict__ labels,
               const unsigned char* __restrict__ valid,
               const float* __restrict__ anchors) {
    const int tid = threadIdx.x;

    __shared__ __align__(128) float s_tile[4][2048];     // 32KB TMA landing
    __shared__ __align__(8)  unsigned long long s_mbar;
    __shared__ float s_w[TPB / 32];

    if (blockIdx.x >= POS_BLOCKS) {
        const int o = blockIdx.x - POS_BLOCKS;
        float acc = 0.0f;

        if (use_tma) {
            // ---------------- TMA path: 32B per cell -----------------------
            const CUtensorMap* tmp; int lo, ng;
            if (o < OBJ_BLK0)                  { tmp = &tm0; lo = o;                       ng = CELLS0 / 4; }
            else if (o < OBJ_BLK0 + OBJ_BLK1)  { tmp = &tm1; lo = o - OBJ_BLK0;            ng = CELLS1 / 4; }
            else                               { tmp = &tm2; lo = o - OBJ_BLK0 - OBJ_BLK1; ng = CELLS2 / 4; }
            const int rowbase = lo * 256;
            const int vr = min(256, ng - rowbase);
            const unsigned int mb =
                (unsigned int)__cvta_generic_to_shared(&s_mbar);

            if (tid == 0)
                asm volatile("mbarrier.init.shared.b64 [%0], %1;"
                             :: "r"(mb), "r"(1) : "memory");
            __syncthreads();
            if (tid == 0) {
                asm volatile("mbarrier.arrive.expect_tx.shared.b64 _, [%0], %1;"
                             :: "r"(mb), "r"(32768u) : "memory");
                const int xoff[4] = {0, 84, 168, 256};
#pragma unroll
                for (int p = 0; p < 4; p++) {
                    const unsigned int dst =
                        (unsigned int)__cvta_generic_to_shared(&s_tile[p][0]);
                    asm volatile(
                        "cp.async.bulk.tensor.2d.shared::cta.global.tile"
                        ".mbarrier::complete_tx::bytes [%0], [%1, {%2, %3}], [%4];"
                        :: "r"(dst), "l"(tmp), "r"(xoff[p]), "r"(rowbase), "r"(mb)
                        : "memory");
                }
            }
            // all threads wait, parity 0, acquire
            asm volatile(
                "{\n\t.reg .pred P;\n"
                "W%=:\n\tmbarrier.try_wait.parity.acquire.cta.shared::cta.b64 P, [%0], %1, 0x989680;\n"
                "\t@P bra D%=;\n\tbra W%=;\nD%=:\n\t}"
                :: "r"(mb), "r"(0u) : "memory");

            if (tid < vr) {
                acc = softplusf(s_tile[0][tid * 8 + 4])
                    + softplusf(s_tile[1][tid * 8 + 5])
                    + softplusf(s_tile[2][tid * 8 + 6])
                    + softplusf(s_tile[3][tid * 8 + 3]);
            }
        } else {
            // ---------------- LDG fallback (R5-proven) ---------------------
            const float* __restrict__ P; int cb, nc;
            if (o < OBJ_BLK0)                  { P = p3; cb = o * 1024;                        nc = CELLS0; }
            else if (o < OBJ_BLK0 + OBJ_BLK1)  { P = p4; cb = (o - OBJ_BLK0) * 1024;           nc = CELLS1; }
            else                               { P = p5; cb = (o - OBJ_BLK0 - OBJ_BLK1) * 1024; nc = CELLS2; }
#pragma unroll
            for (int k = 0; k < 4; k++) {
                const int idx = cb + k * TPB + tid;
                if (idx < nc)
                    acc += softplusf(__ldg(&P[(long)idx * CH_ + 4]));
            }
        }

        // block tree reduce -> one plain store to distinct slot
#pragma unroll
        for (int s = 16; s > 0; s >>= 1)
            acc += __shfl_down_sync(0xFFFFFFFFu, acc, s);
        if ((tid & 31) == 0) s_w[tid >> 5] = acc;
        __syncthreads();
        if (tid < 32) {
            float r = (tid < TPB / 32) ? s_w[tid] : 0.0f;
#pragma unroll
            for (int s = 4; s > 0; s >>= 1)
                r += __shfl_down_sync(0xFFFFFFFFu, r, s);
            if (tid == 0) g_obj[o] = r;
        }
        return;
    }

    // ================= positives: 4 blocks per layer, 1 box/thread ==========
    __shared__ int   s_hash[HASH_SZ];
    __shared__ float s_rc[TPB / 32], s_rb[TPB / 32], s_rn[TPB / 32];
    __shared__ int   s_rp[TPB / 32];

#pragma unroll
    for (int k = 0; k < HASH_SZ / TPB; k++) s_hash[k * TPB + tid] = -1;
    __syncthreads();

    const int layer   = blockIdx.x >> 2;
    const int quarter = blockIdx.x & 3;
    const int i = quarter * TPB + tid;     // box index b*M + m
    const int b = i >> 6;
    const int g = 80 >> layer;
    const float gf = (float)g;
    const float* __restrict__ P = (layer == 0) ? p3 : (layer == 1) ? p4 : p5;
    const float aw0 = __ldg(&anchors[layer * 6 + 0]), ah0 = __ldg(&anchors[layer * 6 + 1]);
    const float aw1 = __ldg(&anchors[layer * 6 + 2]), ah1 = __ldg(&anchors[layer * 6 + 3]);
    const float aw2 = __ldg(&anchors[layer * 6 + 4]), ah2 = __ldg(&anchors[layer * 6 + 5]);

    const float x1 = boxes[i * 4 + 0];
    const float y1 = boxes[i * 4 + 1];
    const float x2 = boxes[i * 4 + 2];
    const float y2 = boxes[i * 4 + 3];
    const float cx = (x1 + x2) * 0.5f * gf;
    const float cy = (y1 + y2) * 0.5f * gf;
    const float w  = (x2 - x1) * gf;
    const float h  = (y2 - y1) * gf;

    const float wh = w * h;
    float best; int ba;
    {
        float in0 = fminf(w, aw0) * fminf(h, ah0);
        float i0  = in0 / (wh + aw0 * ah0 - in0 + 1e-6f);
        float in1 = fminf(w, aw1) * fminf(h, ah1);
        float i1  = in1 / (wh + aw1 * ah1 - in1 + 1e-6f);
        float in2 = fminf(w, aw2) * fminf(h, ah2);
        float i2  = in2 / (wh + aw2 * ah2 - in2 + 1e-6f);
        best = i0; ba = 0;
        if (i1 > best) { best = i1; ba = 1; }
        if (i2 > best) { best = i2; ba = 2; }
    }

    float cls_acc = 0.0f, box_acc = 0.0f, ngx_acc = 0.0f;
    int   np = 0;

    if (valid[i] && best > 0.5f) {
        int gx = (int)cx; gx = min(max(gx, 0), g - 1);
        int gy = (int)cy; gy = min(max(gy, 0), g - 1);
        const int  cell = ((b * A_ + ba) * g + gy) * g + gx;
        const long base = (long)cell * CH_;

        np = 1;

        const int lab = labels[i];
        float cl = 0.0f;
#pragma unroll 4
        for (int c = 0; c < NC_; c++)
            cl += softplusf(__ldg(&P[base + 5 + c]));
        cl -= __ldg(&P[base + 5 + lab]);
        cls_acc = cl;

        const float pcx0 = P[base + 0], pcy0 = P[base + 1];
        const float pw   = P[base + 2], ph   = P[base + 3];
        const float px1 = pcx0 - pw * 0.5f, py1 = pcy0 - ph * 0.5f;
        const float px2 = pcx0 + pw * 0.5f, py2 = pcy0 + ph * 0.5f;
        const float tx1 = cx - w * 0.5f, ty1 = cy - h * 0.5f;
        const float tx2 = cx + w * 0.5f, ty2 = cy + h * 0.5f;

        const float ix1 = fmaxf(px1, tx1), iy1 = fmaxf(py1, ty1);
        const float ix2 = fminf(px2, tx2), iy2 = fminf(py2, ty2);
        const float inter = fmaxf(ix2 - ix1, 0.0f) * fmaxf(iy2 - iy1, 0.0f);
        const float a1 = (px2 - px1) * (py2 - py1);
        const float a2 = (tx2 - tx1) * (ty2 - ty1);
        const float iou = inter / (a1 + a2 - inter + 1e-7f);

        const float pcx = (px1 + px2) * 0.5f, pcy = (py1 + py2) * 0.5f;
        const float tcx = (tx1 + tx2) * 0.5f, tcy = (ty1 + ty2) * 0.5f;
        const float cd  = (pcx - tcx) * (pcx - tcx) + (pcy - tcy) * (pcy - tcy);

        const float ex1 = fminf(px1, tx1), ey1 = fminf(py1, ty1);
        const float ex2 = fmaxf(px2, tx2), ey2 = fmaxf(py2, ty2);
        const float dd  = (ex2 - ex1) * (ex2 - ex1) + (ey2 - ey1) * (ey2 - ey1);

        box_acc = 1.0f - (iou - cd / (dd + 1e-7f));

        unsigned int hsh = (((unsigned int)cell * 2654435761u) >> 23) & (HASH_SZ - 1);
        bool owner = false;
        for (;;) {
            int old = atomicCAS(&s_hash[hsh], -1, cell);
            if (old == -1) { owner = true; break; }
            if (old == cell) break;
            hsh = (hsh + 1) & (HASH_SZ - 1);
        }
        if (owner) ngx_acc = -P[base + 4];
    }

#pragma unroll
    for (int s = 16; s > 0; s >>= 1) {
        cls_acc += __shfl_down_sync(0xFFFFFFFFu, cls_acc, s);
        box_acc += __shfl_down_sync(0xFFFFFFFFu, box_acc, s);
        ngx_acc += __shfl_down_sync(0xFFFFFFFFu, ngx_acc, s);
        np      += __shfl_down_sync(0xFFFFFFFFu, np, s);
    }
    if ((tid & 31) == 0) {
        s_rc[tid >> 5] = cls_acc;
        s_rb[tid >> 5] = box_acc;
        s_rn[tid >> 5] = ngx_acc;
        s_rp[tid >> 5] = np;
    }
    __syncthreads();
    if (tid < 32) {
        float rc = (tid < TPB / 32) ? s_rc[tid] : 0.0f;
        float rb = (tid < TPB / 32) ? s_rb[tid] : 0.0f;
        float rn = (tid < TPB / 32) ? s_rn[tid] : 0.0f;
        int   rp = (tid < TPB / 32) ? s_rp[tid] : 0;
#pragma unroll
        for (int s = 4; s > 0; s >>= 1) {
            rc += __shfl_down_sync(0xFFFFFFFFu, rc, s);
            rb += __shfl_down_sync(0xFFFFFFFFu, rb, s);
            rn += __shfl_down_sync(0xFFFFFFFFu, rn, s);
            rp += __shfl_down_sync(0xFFFFFFFFu, rp, s);
        }
        if (tid == 0) {
            g_pcls[blockIdx.x] = rc;
            g_pbox[blockIdx.x] = rb;
            g_pngx[blockIdx.x] = rn;
            g_pnp [blockIdx.x] = rp;
        }
    }
}

// ---------------------------------------------------------------------------
__global__ void __launch_bounds__(512)
dl_fin_kernel(float* __restrict__ out) {
    const int tid = threadIdx.x;

    double a0 = 0.0, a1 = 0.0, a2 = 0.0;
    if (tid < OBJ_BLOCKS) {
        const double v = (double)g_obj[tid];
        if (tid < OBJ_BLK0)                 a0 = v;
        else if (tid < OBJ_BLK0 + OBJ_BLK1) a1 = v;
        else                                a2 = v;
    }
#pragma unroll
    for (int s = 16; s > 0; s >>= 1) {
        a0 += __shfl_down_sync(0xFFFFFFFFu, a0, s);
        a1 += __shfl_down_sync(0xFFFFFFFFu, a1, s);
        a2 += __shfl_down_sync(0xFFFFFFFFu, a2, s);
    }
    __shared__ double s_f[3][16];
    if ((tid & 31) == 0) {
        s_f[0][tid >> 5] = a0;
        s_f[1][tid >> 5] = a1;
        s_f[2][tid >> 5] = a2;
    }
    __syncthreads();

    if (tid == 0) {
        double sp[3] = {0.0, 0.0, 0.0};
#pragma unroll
        for (int k = 0; k < 16; k++) {
            sp[0] += s_f[0][k];
            sp[1] += s_f[1][k];
            sp[2] += s_f[2][k];
        }
        const double ncell[3] = {(double)CELLS0, (double)CELLS1, (double)CELLS2};
        double cls = 0.0, obj = 0.0, box = 0.0;
#pragma unroll
        for (int l = 0; l < 3; l++) {
            double pc = 0.0, pb = 0.0, pn = 0.0;
            int np = 0;
#pragma unroll
            for (int q = 0; q < 4; q++) {
                pc += (double)g_pcls[l * 4 + q];
                pb += (double)g_pbox[l * 4 + q];
                pn += (double)g_pngx[l * 4 + q];
                np += g_pnp[l * 4 + q];
            }
            if (np > 0) {
                const double denom = (double)np;
                cls += pc / (denom * (double)NC_);
                obj += (sp[l] + pn) / ncell[l];
                box += pb / denom;
            }
        }
        out[0] = (float)(0.5 * cls + 1.0 * obj + 0.05 * box);
    }
}

// ---------------------------------------------------------------------------
typedef CUresult (*cuTensorMapEncodeTiled_t)(
    CUtensorMap*, CUtensorMapDataType, cuuint32_t, void*,
    const cuuint64_t*, const cuuint64_t*, const cuuint32_t*, const cuuint32_t*,
    CUtensorMapInterleave, CUtensorMapSwizzle, CUtensorMapL2promotion,
    CUtensorMapFloatOOBfill);

static CUresult build_map(CUtensorMap* tm, cuTensorMapEncodeTiled_t enc,
                          const float* base, unsigned long long ngroups) {
    cuuint64_t dims[2]    = {340ull, ngroups};       // floats; 4 cells per row
    cuuint64_t strides[1] = {1360ull};               // bytes; multiple of 16
    cuuint32_t box[2]     = {8u, 256u};              // 32B x 256 rows
    cuuint32_t es[2]      = {1u, 1u};
    return enc(tm, CU_TENSOR_MAP_DATA_TYPE_FLOAT32, 2, (void*)base,
               dims, strides, box, es,
               CU_TENSOR_MAP_INTERLEAVE_NONE, CU_TENSOR_MAP_SWIZZLE_NONE,
               CU_TENSOR_MAP_L2_PROMOTION_NONE,
               CU_TENSOR_MAP_FLOAT_OOB_FILL_NONE);
}

extern "C" void kernel_launch(void* const* d_in, const int* in_sizes, int n_in,
                              void* d_out, int out_size) {
    const float*         p3      = (const float*)d_in[0];
    const float*         p4      = (const float*)d_in[1];
    const float*         p5      = (const float*)d_in[2];
    const float*         boxes   = (const float*)d_in[3];
    const int*           labels  = (const int*)d_in[4];
    const unsigned char* valid   = (const unsigned char*)d_in[5];
    const float*         anchors = (const float*)d_in[6];
    float*               out     = (float*)d_out;

    CUtensorMap tm0, tm1, tm2;
    memset(&tm0, 0, sizeof(tm0));
    memset(&tm1, 0, sizeof(tm1));
    memset(&tm2, 0, sizeof(tm2));
    int use_tma = 0;

    void* sym = nullptr;
    cudaDriverEntryPointQueryResult qr = cudaDriverEntryPointSymbolNotFound;
    if (cudaGetDriverEntryPoint("cuTensorMapEncodeTiled", &sym,
                                cudaEnableDefault, &qr) == cudaSuccess &&
        sym != nullptr) {
        cuTensorMapEncodeTiled_t enc = (cuTensorMapEncodeTiled_t)sym;
        CUresult r0 = build_map(&tm0, enc, p3, CELLS0 / 4);
        CUresult r1 = build_map(&tm1, enc, p4, CELLS1 / 4);
        CUresult r2 = build_map(&tm2, enc, p5, CELLS2 / 4);
        if (r0 == CUDA_SUCCESS && r1 == CUDA_SUCCESS && r2 == CUDA_SUCCESS)
            use_tma = 1;
    }

    dl_main_kernel<<<TOTAL_BLOCKS, TPB>>>(tm0, tm1, tm2, use_tma,
                                          p3, p4, p5, boxes, labels, valid,
                                          anchors);
    dl_fin_kernel<<<1, 512>>>(out);
}